// round 12
// baseline (speedup 1.0000x reference)
#include <cuda_runtime.h>
#include <cuda_bf16.h>
#include <math.h>

#define BATCH   16384
#define NTAB    26
#define VOCABSZ 100000

typedef unsigned long long u64;
typedef unsigned int       u32;
typedef unsigned short     u16;

// ---------------- scratch (bss, zero-initialized, no allocation) --------
__device__ u16   g_x0h[BATCH * 512], g_x0l[BATCH * 512];   // bottom L0 out (split)
__device__ u16   g_x1h[BATCH * 256], g_x1l[BATCH * 256];   // bottom L1 out (split)
__device__ float g_d  [BATCH * 64];                        // bottom L2 out (fp32 d)
__device__ u16   g_hh [BATCH * 416], g_hl [BATCH * 416];   // split h (d|inter|pad), K=416
__device__ u16   g_h1h[BATCH * 512], g_h1l[BATCH * 512];   // top L0 out (split)
__device__ float g_sp [BATCH * 26 * 64];                   // gathered embeddings (fp32)
// transposed + split bf16 weights  (Wt[n][k] = W[k][n]; k >= Kreal zeroed)
__device__ u16 g_Wb1h[256 * 512], g_Wb1l[256 * 512];
__device__ u16 g_Wb2h[ 64 * 256], g_Wb2l[ 64 * 256];
__device__ u16 g_Wt0h[512 * 416], g_Wt0l[512 * 416];
__device__ u16 g_Wt1h[256 * 512], g_Wt1l[256 * 512];

// ---------------- helpers ----------------
__device__ __forceinline__ u32 smem_u32(const void* p) {
    u32 a;
    asm("{ .reg .u64 t; cvta.to.shared.u64 t, %1; cvt.u32.u64 %0, t; }"
        : "=r"(a) : "l"(p));
    return a;
}

// split fp32 pair (a,b) into packed bf16 hi (a->lo half) and bf16 residuals
__device__ __forceinline__ void split2(float a, float b, u32& hi, u32& lo) {
    asm("cvt.rn.bf16x2.f32 %0, %1, %2;" : "=r"(hi) : "f"(b), "f"(a));
    float ra = a - __uint_as_float(hi << 16);
    float rb = b - __uint_as_float(hi & 0xFFFF0000u);
    asm("cvt.rn.bf16x2.f32 %0, %1, %2;" : "=r"(lo) : "f"(rb), "f"(ra));
}

__device__ __forceinline__ void ldmx4(u32* r, u32 addr) {
    asm volatile("ldmatrix.sync.aligned.m8n8.x4.shared.b16 {%0,%1,%2,%3}, [%4];"
                 : "=r"(r[0]), "=r"(r[1]), "=r"(r[2]), "=r"(r[3]) : "r"(addr));
}
__device__ __forceinline__ void mma16816(float* c, const u32* a, const u32* b) {
    asm volatile(
        "mma.sync.aligned.m16n8k16.row.col.f32.bf16.bf16.f32 "
        "{%0,%1,%2,%3}, {%4,%5,%6,%7}, {%8,%9}, {%0,%1,%2,%3};"
        : "+f"(c[0]), "+f"(c[1]), "+f"(c[2]), "+f"(c[3])
        : "r"(a[0]), "r"(a[1]), "r"(a[2]), "r"(a[3]), "r"(b[0]), "r"(b[1]));
}
__device__ __forceinline__ void cp16(u32 dst, const void* src) {
    asm volatile("cp.async.cg.shared.global [%0], [%1], 16;"
                 :: "r"(dst), "l"(__cvta_generic_to_global(src)));
}
// 256-byte bulk async copy, completion via mbarrier complete_tx
__device__ __forceinline__ void cpbulk256(u32 dst, const void* src, u32 mbar) {
    asm volatile(
        "cp.async.bulk.shared::cta.global.mbarrier::complete_tx::bytes "
        "[%0], [%1], 256, [%2];"
        :: "r"(dst), "l"(__cvta_generic_to_global(src)), "r"(mbar) : "memory");
}

// =====================================================================
// Weight prep (single launch): all 4 weights transposed + split.
// =====================================================================
__global__ void __launch_bounds__(256) prep_all(
    const float* __restrict__ Wb1, const float* __restrict__ Wb2,
    const float* __restrict__ Wt0, const float* __restrict__ Wt1,
    u16* __restrict__ b1h, u16* __restrict__ b1l,
    u16* __restrict__ b2h, u16* __restrict__ b2l,
    u16* __restrict__ t0h, u16* __restrict__ t0l,
    u16* __restrict__ t1h, u16* __restrict__ t1l)
{
    const int i = blockIdx.x * 256 + threadIdx.x;
    const float* W; u16 *H, *L; int N, Kreal, Kpad, li;
    if (i < 16384)      { W = Wb1; H = b1h; L = b1l; N = 256; Kreal = 512; Kpad = 512; li = i; }
    else if (i < 18432) { W = Wb2; H = b2h; L = b2l; N =  64; Kreal = 256; Kpad = 256; li = i - 16384; }
    else if (i < 45056) { W = Wt0; H = t0h; L = t0l; N = 512; Kreal = 415; Kpad = 416; li = i - 18432; }
    else if (i < 61440) { W = Wt1; H = t1h; L = t1l; N = 256; Kreal = 512; Kpad = 512; li = i - 45056; }
    else return;
    const int n  = li / (Kpad / 8);
    const int k8 = (li % (Kpad / 8)) * 8;
    u16 hb[8], lb[8];
#pragma unroll
    for (int j = 0; j < 8; j++) {
        const int k = k8 + j;
        const float w = (k < Kreal) ? W[(size_t)k * N + n] : 0.f;
        u32 h, l;
        split2(w, 0.f, h, l);
        hb[j] = (u16)(h & 0xFFFFu);
        lb[j] = (u16)(l & 0xFFFFu);
    }
    *(uint4*)(H + (size_t)n * Kpad + k8) = *(uint4*)hb;
    *(uint4*)(L + (size_t)n * Kpad + k8) = *(uint4*)lb;
}

// =====================================================================
// Warp-MMA split-bf16 GEMM (proven mainloop).
// OMODE: 0 = fp32 C; 1 = split bf16; 2 = both; 3 = fused final sigmoid.
// =====================================================================
template<int THREADS, int BN, int OMODE, int NSTAGE>
__global__ void __launch_bounds__(THREADS, (THREADS == 256 ? 2 : 1))
gemm_mma(
    const u16* __restrict__ Ah, const u16* __restrict__ Al, int Kpad,
    const u16* __restrict__ Bh, const u16* __restrict__ Bl,
    const float* __restrict__ bias,
    float* __restrict__ C, int ldc,
    u16* __restrict__ Oh, u16* __restrict__ Ol, int Kout,
    int NC,
    float* __restrict__ out2, const float* __restrict__ w2,
    const float* __restrict__ b2)
{
    constexpr int SR  = 40;
    constexpr int WNC = THREADS / 128;
    constexpr int NW  = BN / WNC;
    constexpr int NFR = NW / 8;
    constexpr int SSZ = (256 + 2 * BN) * SR;
    extern __shared__ u16 sm[];
    const u32 sbase = smem_u32(sm);
    const int tid = threadIdx.x, wid = tid >> 5, lane = tid & 31;
    const int wm = wid & 3, wn = wid >> 2;
    const int bm = blockIdx.y * 128, bn = blockIdx.x * BN;

    float acc[2][NFR][4];
#pragma unroll
    for (int m = 0; m < 2; m++)
#pragma unroll
        for (int n = 0; n < NFR; n++)
#pragma unroll
            for (int j = 0; j < 4; j++) acc[m][n][j] = 0.f;

    auto prefetch = [&](int c, int buf) {
        const u32 sb = sbase + (u32)buf * SSZ * 2;
        constexpr int AOPS = 1024 / THREADS;
#pragma unroll
        for (int i = 0; i < AOPS; i++) {
            const int g = tid + i * THREADS;
            const int arr = g >> 9, r = (g >> 2) & 127, ch = g & 3;
            const u16* src = (arr ? Al : Ah) + (size_t)(bm + r) * Kpad + c * 32 + ch * 8;
            cp16(sb + (u32)(arr * 128 * SR + r * SR + ch * 8) * 2, src);
        }
        constexpr int BOPS = BN * 8 / THREADS;
#pragma unroll
        for (int i = 0; i < BOPS; i++) {
            const int g = tid + i * THREADS;
            const int arr = g / (BN * 4), r = (g >> 2) & (BN - 1), ch = g & 3;
            const u16* src = (arr ? Bl : Bh) + (size_t)(bn + r) * Kpad + c * 32 + ch * 8;
            cp16(sb + (u32)((256 + arr * BN) * SR + r * SR + ch * 8) * 2, src);
        }
    };

    prefetch(0, 0);
    asm volatile("cp.async.commit_group;" ::: "memory");
    if (NSTAGE == 3) {
        prefetch(1, 1);
        asm volatile("cp.async.commit_group;" ::: "memory");
    }

    for (int c = 0; c < NC; c++) {
        asm volatile("cp.async.wait_group %0;" :: "n"(NSTAGE - 2) : "memory");
        __syncthreads();
        if (c + NSTAGE - 1 < NC) prefetch(c + NSTAGE - 1, (c + NSTAGE - 1) % NSTAGE);
        asm volatile("cp.async.commit_group;" ::: "memory");

        const u32 sA  = sbase + (u32)(c % NSTAGE) * SSZ * 2;
        const u32 sBs = sA + 256 * SR * 2;
#pragma unroll
        for (int ks = 0; ks < 2; ks++) {
            u32 ah[2][4], al_[2][4];
#pragma unroll
            for (int mf = 0; mf < 2; mf++) {
                const u32 ra = sA + (u32)(((wm * 32 + mf * 16 + (lane & 15)) * SR
                                           + ks * 16 + (lane >> 4) * 8) * 2);
                ldmx4(ah[mf], ra);
                ldmx4(al_[mf], ra + 128 * SR * 2);
            }
#pragma unroll
            for (int nf2 = 0; nf2 < NFR / 2; nf2++) {
                const u32 rb = sBs + (u32)(((wn * NW + nf2 * 16 + (lane & 7)
                                             + ((lane >> 4) << 3)) * SR
                                            + ks * 16 + ((lane >> 3) & 1) * 8) * 2);
                u32 bh4[4], bl4[4];
                ldmx4(bh4, rb);
                ldmx4(bl4, rb + BN * SR * 2);
#pragma unroll
                for (int hf = 0; hf < 2; hf++) {
                    const int nf = nf2 * 2 + hf;
                    const u32* bh2 = bh4 + hf * 2;
                    const u32* bl2 = bl4 + hf * 2;
#pragma unroll
                    for (int mf = 0; mf < 2; mf++) {
                        mma16816(acc[mf][nf], ah[mf],  bh2);
                        mma16816(acc[mf][nf], ah[mf],  bl2);
                        mma16816(acc[mf][nf], al_[mf], bh2);
                    }
                }
            }
        }
    }

    if (OMODE == 3) {
        asm volatile("cp.async.wait_group 0;" ::: "memory");
        __syncthreads();
        float* srow = (float*)sm;
        if (tid < 128) srow[tid] = 0.f;
        __syncthreads();
        float p[4] = {0.f, 0.f, 0.f, 0.f};
#pragma unroll
        for (int mf = 0; mf < 2; mf++) {
#pragma unroll
            for (int nf = 0; nf < NFR; nf++) {
                const int cc = bn + wn * NW + nf * 8 + 2 * (lane & 3);
                const float b0 = bias[cc], b1 = bias[cc + 1];
                const float w0 = w2[cc], w1 = w2[cc + 1];
                const float v0 = fmaxf(acc[mf][nf][0] + b0, 0.f);
                const float v1 = fmaxf(acc[mf][nf][1] + b1, 0.f);
                const float v2 = fmaxf(acc[mf][nf][2] + b0, 0.f);
                const float v3 = fmaxf(acc[mf][nf][3] + b1, 0.f);
                p[mf * 2 + 0] += v0 * w0 + v1 * w1;
                p[mf * 2 + 1] += v2 * w0 + v3 * w1;
            }
        }
#pragma unroll
        for (int s = 1; s <= 2; s <<= 1)
#pragma unroll
            for (int j = 0; j < 4; j++)
                p[j] += __shfl_xor_sync(0xffffffffu, p[j], s);
        if ((lane & 3) == 0) {
            const int r0 = wm * 32 + (lane >> 2);
            atomicAdd(&srow[r0],      p[0]);
            atomicAdd(&srow[r0 + 8],  p[1]);
            atomicAdd(&srow[r0 + 16], p[2]);
            atomicAdd(&srow[r0 + 24], p[3]);
        }
        __syncthreads();
        if (tid < 128)
            out2[bm + tid] = 1.f / (1.f + expf(-(srow[tid] + b2[0])));
    } else {
#pragma unroll
        for (int mf = 0; mf < 2; mf++) {
#pragma unroll
            for (int nf = 0; nf < NFR; nf++) {
                const int row0 = bm + wm * 32 + mf * 16 + (lane >> 2);
                const int cc   = bn + wn * NW + nf * 8 + 2 * (lane & 3);
                const float b0 = bias[cc], b1 = bias[cc + 1];
                const float v0 = fmaxf(acc[mf][nf][0] + b0, 0.f);
                const float v1 = fmaxf(acc[mf][nf][1] + b1, 0.f);
                const float v2 = fmaxf(acc[mf][nf][2] + b0, 0.f);
                const float v3 = fmaxf(acc[mf][nf][3] + b1, 0.f);
                if (OMODE != 1) {
                    *(float2*)(C + (size_t)row0 * ldc + cc)       = make_float2(v0, v1);
                    *(float2*)(C + (size_t)(row0 + 8) * ldc + cc) = make_float2(v2, v3);
                }
                if (OMODE != 0) {
                    u32 h, l;
                    split2(v0, v1, h, l);
                    *(u32*)(Oh + (size_t)row0 * Kout + cc) = h;
                    *(u32*)(Ol + (size_t)row0 * Kout + cc) = l;
                    split2(v2, v3, h, l);
                    *(u32*)(Oh + (size_t)(row0 + 8) * Kout + cc) = h;
                    *(u32*)(Ol + (size_t)(row0 + 8) * Kout + cc) = l;
                }
            }
        }
    }
}

// =====================================================================
// Bottom MLP layer 0: x0 = relu(dense[16384,13] @ Wb0 + bb0), split-bf16 out
// =====================================================================
__global__ void __launch_bounds__(256) bot0_kernel(
    const float* __restrict__ dense, const float* __restrict__ W,
    const float* __restrict__ bias, u16* __restrict__ xh, u16* __restrict__ xl)
{
    __shared__ float sW[13 * 512];
    __shared__ float sB[512];
    __shared__ float sD[32 * 13];
    const int tid = threadIdx.x;
    const int rbase = blockIdx.x * 32;

    for (int i = tid; i < 13 * 512; i += 256) sW[i] = W[i];
    for (int i = tid; i < 512;      i += 256) sB[i] = bias[i];
    for (int i = tid; i < 32 * 13;  i += 256) sD[i] = dense[(size_t)rbase * 13 + i];
    __syncthreads();

    const int q  = tid & 127;
    const int rs = tid >> 7;
    const int c0 = q * 4;

    float4 w[13];
#pragma unroll
    for (int k = 0; k < 13; k++) w[k] = *(const float4*)&sW[k * 512 + c0];
    const float4 bq = *(const float4*)&sB[c0];

    for (int rr = 0; rr < 16; rr++) {
        const int r = rs * 16 + rr;
        float4 acc = bq;
#pragma unroll
        for (int k = 0; k < 13; k++) {
            const float a = sD[r * 13 + k];
            acc.x += a * w[k].x; acc.y += a * w[k].y;
            acc.z += a * w[k].z; acc.w += a * w[k].w;
        }
        acc.x = fmaxf(acc.x, 0.f); acc.y = fmaxf(acc.y, 0.f);
        acc.z = fmaxf(acc.z, 0.f); acc.w = fmaxf(acc.w, 0.f);
        u32 h0, l0, h1, l1;
        split2(acc.x, acc.y, h0, l0);
        split2(acc.z, acc.w, h1, l1);
        const size_t o = (size_t)(rbase + r) * 512 + c0;
        *(uint2*)(xh + o) = make_uint2(h0, h1);
        *(uint2*)(xl + o) = make_uint2(l0, l1);
    }
}

// =====================================================================
// interact_e: embedding gather (bulk) + pairs among 26 embeddings only
// (i<26). Also dumps gathered embeddings to sp (fp32) for interact_d.
// Independent of the bottom MLP -> runs on a forked stream.
// =====================================================================
#define EROWS 8

__global__ void __launch_bounds__(256) interact_e(
    const u64* __restrict__ sidx, const float* __restrict__ emb,
    float* __restrict__ sp,
    u16* __restrict__ hh, u16* __restrict__ hl)
{
    extern __shared__ float Tsh[];
    __shared__ u64 mbar_store;
    __shared__ int s_is32;
    float4* T4 = (float4*)Tsh;
    const u32 sbase = smem_u32(Tsh);
    const u32 mbar  = smem_u32(&mbar_store);
    const int tid = threadIdx.x;
    const int rbase = blockIdx.x * EROWS;

    if (tid == 0) {
        int f = 0;
#pragma unroll
        for (int i = 0; i < 16; i++)
            if (sidx[i] >> 32) f = 1;
        s_is32 = f;
        asm volatile("mbarrier.init.shared.b64 [%0], 1;" :: "r"(mbar) : "memory");
    }
    __syncthreads();
    if (tid == 0) {
        asm volatile("mbarrier.arrive.expect_tx.shared.b64 _, [%0], %1;"
                     :: "r"(mbar), "r"((u32)(EROWS * 26 * 256)) : "memory");
    }
    __syncthreads();
    const bool is32 = (s_is32 != 0);
    const int* sidx32 = (const int*)sidx;

    if (tid < EROWS * 26) {
        const int r = tid / 26, t = tid - r * 26;
        long long idx;
        if (is32) idx = (long long)sidx32[(rbase + r) * 26 + t];
        else      idx = (long long)sidx[(rbase + r) * 26 + t];
        cpbulk256(sbase + (u32)((r * 28 + t) * 272),
                  emb + ((size_t)t * VOCABSZ + (size_t)idx) * 64, mbar);
    }
    // zero pad vectors 26, 27
    for (int u = tid; u < EROWS * 32; u += 256) {
        const int r = u >> 5, rem = u & 31;
        T4[(r * 28 + 26 + (rem >> 4)) * 17 + (rem & 15)] =
            make_float4(0.f, 0.f, 0.f, 0.f);
    }
    {
        u32 done;
        asm volatile(
            "{\n\t.reg .pred p;\n\t"
            "mbarrier.try_wait.parity.acquire.cta.shared::cta.b64 p, [%1], 0;\n\t"
            "selp.b32 %0, 1, 0, p;\n\t}"
            : "=r"(done) : "r"(mbar) : "memory");
        if (!done) {
            asm volatile(
                "{\n\t.reg .pred P;\n"
                "WL_%=:\n\t"
                "mbarrier.try_wait.parity.acquire.cta.shared::cta.b64 P, [%0], 0, 0x989680;\n\t"
                "@P bra WD_%=;\n\t"
                "bra WL_%=;\n"
                "WD_%=:\n\t}"
                :: "r"(mbar) : "memory");
        }
    }
    __syncthreads();

    // dump gathered embeddings to sp (fp32, coalesced)
    for (int u = tid; u < EROWS * 26 * 16; u += 256) {
        const int v = u >> 4, f = u & 15;
        const int r = v / 26, t = v - r * 26;
        ((float4*)sp)[(((size_t)(rbase + r) * 26 + t) << 4) + f] =
            T4[(r * 28 + t) * 17 + f];
    }

    // pairs among embeddings only: write guard i < 26
    const int task = tid;
    if (task < EROWS * 28) {
        const int r = task / 28, tt = task - r * 28;
        const int grow = rbase + r;
        u16* hrh = hh + (size_t)grow * 416 + 64;
        u16* hrl = hl + (size_t)grow * 416 + 64;
        const float4* bb = T4 + (size_t)r * 28 * 17;

        if (tt < 21) {
            int ti = 1;
            while ((ti * (ti + 1)) / 2 <= tt) ti++;
            const int tj = tt - ti * (ti - 1) / 2;
            const float4* Ti = bb + (4 * ti) * 17;
            const float4* Tj = bb + (4 * tj) * 17;
            float a[4][4];
#pragma unroll
            for (int ii = 0; ii < 4; ii++)
#pragma unroll
                for (int jj = 0; jj < 4; jj++) a[ii][jj] = 0.f;
#pragma unroll
            for (int f = 0; f < 16; f++) {
                float4 x[4], y[4];
#pragma unroll
                for (int ii = 0; ii < 4; ii++) x[ii] = Ti[ii * 17 + f];
#pragma unroll
                for (int jj = 0; jj < 4; jj++) y[jj] = Tj[jj * 17 + f];
#pragma unroll
                for (int ii = 0; ii < 4; ii++)
#pragma unroll
                    for (int jj = 0; jj < 4; jj++)
                        a[ii][jj] += x[ii].x * y[jj].x + x[ii].y * y[jj].y
                                   + x[ii].z * y[jj].z + x[ii].w * y[jj].w;
            }
#pragma unroll
            for (int ii = 0; ii < 4; ii++) {
                const int i = 4 * ti + ii;
                if (i < 26) {
                    const int base_i = i * (i - 1) / 2;
#pragma unroll
                    for (int jj = 0; jj < 4; jj++) {
                        const int j = 4 * tj + jj;
                        u32 h, l;
                        split2(a[ii][jj], 0.f, h, l);
                        hrh[base_i + j] = (u16)h;
                        hrl[base_i + j] = (u16)l;
                    }
                }
            }
        } else {
            const int ti = tt - 21;
            const float4* Ti = bb + (4 * ti) * 17;
            float a[6];
#pragma unroll
            for (int p = 0; p < 6; p++) a[p] = 0.f;
#pragma unroll
            for (int f = 0; f < 16; f++) {
                float4 x[4];
#pragma unroll
                for (int ii = 0; ii < 4; ii++) x[ii] = Ti[ii * 17 + f];
                a[0] += x[1].x * x[0].x + x[1].y * x[0].y + x[1].z * x[0].z + x[1].w * x[0].w;
                a[1] += x[2].x * x[0].x + x[2].y * x[0].y + x[2].z * x[0].z + x[2].w * x[0].w;
                a[2] += x[2].x * x[1].x + x[2].y * x[1].y + x[2].z * x[1].z + x[2].w * x[1].w;
                a[3] += x[3].x * x[0].x + x[3].y * x[0].y + x[3].z * x[0].z + x[3].w * x[0].w;
                a[4] += x[3].x * x[1].x + x[3].y * x[1].y + x[3].z * x[1].z + x[3].w * x[1].w;
                a[5] += x[3].x * x[2].x + x[3].y * x[2].y + x[3].z * x[2].z + x[3].w * x[2].w;
            }
            const int pi[6] = {1, 2, 2, 3, 3, 3};
            const int pj[6] = {0, 0, 1, 0, 1, 2};
#pragma unroll
            for (int p = 0; p < 6; p++) {
                const int i = 4 * ti + pi[p], j = 4 * ti + pj[p];
                if (i < 26) {
                    u32 h, l;
                    split2(a[p], 0.f, h, l);
                    hrh[i * (i - 1) / 2 + j] = (u16)h;
                    hrl[i * (i - 1) / 2 + j] = (u16)l;
                }
            }
        }
    }
}

// =====================================================================
// interact_d: the 26 d-pairs per row: h[26-row block] = e_j . d
// Reads sp (coalesced via smem) + d; writes split-bf16 cols 389..414.
// =====================================================================
#define DROWS 4

__global__ void __launch_bounds__(256) interact_d(
    const float* __restrict__ sp, const float* __restrict__ dvec,
    u16* __restrict__ hh, u16* __restrict__ hl)
{
    __shared__ float sS[DROWS * 26 * 64];
    __shared__ float sD[DROWS * 64];
    const int tid = threadIdx.x;
    const int rbase = blockIdx.x * DROWS;

    for (int i = tid; i < DROWS * 26 * 16; i += 256)
        ((float4*)sS)[i] = ((const float4*)(sp + (size_t)rbase * 26 * 64))[i];
    for (int i = tid; i < DROWS * 16; i += 256)
        ((float4*)sD)[i] = ((const float4*)(dvec + (size_t)rbase * 64))[i];
    __syncthreads();

    if (tid < DROWS * 26) {
        const int r = tid / 26, j = tid - r * 26;
        const float4* e = (const float4*)(sS + (r * 26 + j) * 64);
        const float4* d = (const float4*)(sD + r * 64);
        float a = 0.f;
#pragma unroll
        for (int f = 0; f < 16; f++) {
            const float4 x = e[f], y = d[f];
            a += x.x * y.x + x.y * y.y + x.z * y.z + x.w * y.w;
        }
        u32 h, l;
        split2(a, 0.f, h, l);
        const size_t o = (size_t)(rbase + r) * 416 + 64 + 325 + j;
        hh[o] = (u16)h;
        hl[o] = (u16)l;
    }
}

// =====================================================================
// launch: forked graph — interact_e runs concurrent with bottom chain.
// =====================================================================
extern "C" void kernel_launch(void* const* d_in, const int* in_sizes, int n_in,
                              void* d_out, int out_size)
{
    const float* dense = (const float*)d_in[0];
    const u64*   sidx  = (const u64*)  d_in[1];
    const float* emb   = (const float*)d_in[2];
    const float* Wb0 = (const float*)d_in[3];  const float* bb0 = (const float*)d_in[4];
    const float* Wb1 = (const float*)d_in[5];  const float* bb1 = (const float*)d_in[6];
    const float* Wb2 = (const float*)d_in[7];  const float* bb2 = (const float*)d_in[8];
    const float* Wt0 = (const float*)d_in[9];  const float* bt0 = (const float*)d_in[10];
    const float* Wt1 = (const float*)d_in[11]; const float* bt1 = (const float*)d_in[12];
    const float* Wt2 = (const float*)d_in[13]; const float* bt2 = (const float*)d_in[14];
    float* out = (float*)d_out;

    u16 *x0h, *x0l, *x1h, *x1l, *hh, *hl, *h1h, *h1l;
    float *dv, *sp;
    cudaGetSymbolAddress((void**)&x0h, g_x0h); cudaGetSymbolAddress((void**)&x0l, g_x0l);
    cudaGetSymbolAddress((void**)&x1h, g_x1h); cudaGetSymbolAddress((void**)&x1l, g_x1l);
    cudaGetSymbolAddress((void**)&dv,  g_d);   cudaGetSymbolAddress((void**)&sp,  g_sp);
    cudaGetSymbolAddress((void**)&hh,  g_hh);  cudaGetSymbolAddress((void**)&hl,  g_hl);
    cudaGetSymbolAddress((void**)&h1h, g_h1h); cudaGetSymbolAddress((void**)&h1l, g_h1l);
    u16 *wb1h, *wb1l, *wb2h, *wb2l, *wt0h, *wt0l, *wt1h, *wt1l;
    cudaGetSymbolAddress((void**)&wb1h, g_Wb1h); cudaGetSymbolAddress((void**)&wb1l, g_Wb1l);
    cudaGetSymbolAddress((void**)&wb2h, g_Wb2h); cudaGetSymbolAddress((void**)&wb2l, g_Wb2l);
    cudaGetSymbolAddress((void**)&wt0h, g_Wt0h); cudaGetSymbolAddress((void**)&wt0l, g_Wt0l);
    cudaGetSymbolAddress((void**)&wt1h, g_Wt1h); cudaGetSymbolAddress((void**)&wt1l, g_Wt1l);

    // dynamic smem opt-in
    const int SM256 = 3 * (256 + 2 * 256) * 40 * 2;   // 184,320 B
    const int SM128 = 2 * (256 + 2 * 128) * 40 * 2;   //  81,920 B
    const int SM64  = 3 * (256 + 2 *  64) * 40 * 2;   //  92,160 B
    const int SMEI  = EROWS * 28 * 68 * 4;            //  60,928 B
    cudaFuncSetAttribute((const void*)gemm_mma<256, 128, 1, 2>,
                         cudaFuncAttributeMaxDynamicSharedMemorySize, SM128);
    cudaFuncSetAttribute((const void*)gemm_mma<512, 64, 2, 3>,
                         cudaFuncAttributeMaxDynamicSharedMemorySize, SM64);
    cudaFuncSetAttribute((const void*)gemm_mma<512, 256, 1, 3>,
                         cudaFuncAttributeMaxDynamicSharedMemorySize, SM256);
    cudaFuncSetAttribute((const void*)gemm_mma<512, 256, 3, 3>,
                         cudaFuncAttributeMaxDynamicSharedMemorySize, SM256);
    cudaFuncSetAttribute((const void*)interact_e,
                         cudaFuncAttributeMaxDynamicSharedMemorySize, SMEI);

    // fork: interact_e on side stream, concurrent with bottom chain.
    cudaStream_t s2;
    cudaStreamCreateWithFlags(&s2, cudaStreamNonBlocking);
    cudaEvent_t evF, evJ;
    cudaEventCreateWithFlags(&evF, cudaEventDisableTiming);
    cudaEventCreateWithFlags(&evJ, cudaEventDisableTiming);

    cudaEventRecord(evF, 0);
    cudaStreamWaitEvent(s2, evF, 0);
    interact_e<<<BATCH / EROWS, 256, SMEI, s2>>>(sidx, emb, sp, hh, hl);
    cudaEventRecord(evJ, s2);

    // main chain
    prep_all<<<240, 256>>>(Wb1, Wb2, Wt0, Wt1,
                           wb1h, wb1l, wb2h, wb2l, wt0h, wt0l, wt1h, wt1l);
    bot0_kernel<<<BATCH / 32, 256>>>(dense, Wb0, bb0, x0h, x0l);
    gemm_mma<256, 128, 1, 2><<<dim3(2, BATCH / 128), 256, SM128>>>(
        x0h, x0l, 512, wb1h, wb1l, bb1, nullptr, 0, x1h, x1l, 256, 16,
        nullptr, nullptr, nullptr);
    gemm_mma<512, 64, 2, 3><<<dim3(1, BATCH / 128), 512, SM64>>>(
        x1h, x1l, 256, wb2h, wb2l, bb2, dv, 64, hh, hl, 416, 8,
        nullptr, nullptr, nullptr);

    // join, then d-pairs + top MLP
    cudaStreamWaitEvent(0, evJ, 0);
    interact_d<<<BATCH / DROWS, 256>>>(sp, dv, hh, hl);

    gemm_mma<512, 256, 1, 3><<<dim3(2, BATCH / 128), 512, SM256>>>(
        hh, hl, 416, wt0h, wt0l, bt0, nullptr, 0, h1h, h1l, 512, 13,
        nullptr, nullptr, nullptr);
    gemm_mma<512, 256, 3, 3><<<dim3(1, BATCH / 128), 512, SM256>>>(
        h1h, h1l, 512, wt1h, wt1l, bt1, nullptr, 0, nullptr, nullptr, 0, 16,
        out, Wt2, bt2);
}

// round 13
// speedup vs baseline: 1.1259x; 1.1259x over previous
#include <cuda_runtime.h>
#include <cuda_bf16.h>
#include <math.h>

#define BATCH   16384
#define NTAB    26
#define VOCABSZ 100000

typedef unsigned long long u64;
typedef unsigned int       u32;
typedef unsigned short     u16;

// ---------------- scratch (bss, zero-initialized, no allocation) --------
__device__ u16   g_x0h[BATCH * 512], g_x0l[BATCH * 512];   // bottom L0 out (split)
__device__ u16   g_x1h[BATCH * 256], g_x1l[BATCH * 256];   // bottom L1 out (split)
__device__ float g_d  [BATCH * 64];                        // bottom L2 out (fp32 d)
__device__ u16   g_hh [BATCH * 416], g_hl [BATCH * 416];   // split h (d|inter|pad), K=416
__device__ u16   g_h1h[BATCH * 512], g_h1l[BATCH * 512];   // top L0 out (split)
// transposed + split bf16 weights  (Wt[n][k] = W[k][n]; k >= Kreal zeroed)
__device__ u16 g_Wb1h[256 * 512], g_Wb1l[256 * 512];
__device__ u16 g_Wb2h[ 64 * 256], g_Wb2l[ 64 * 256];
__device__ u16 g_Wt0h[512 * 416], g_Wt0l[512 * 416];
__device__ u16 g_Wt1h[256 * 512], g_Wt1l[256 * 512];

// ---------------- helpers ----------------
__device__ __forceinline__ u32 smem_u32(const void* p) {
    u32 a;
    asm("{ .reg .u64 t; cvta.to.shared.u64 t, %1; cvt.u32.u64 %0, t; }"
        : "=r"(a) : "l"(p));
    return a;
}

// split fp32 pair (a,b) into packed bf16 hi (a->lo half) and bf16 residuals
__device__ __forceinline__ void split2(float a, float b, u32& hi, u32& lo) {
    asm("cvt.rn.bf16x2.f32 %0, %1, %2;" : "=r"(hi) : "f"(b), "f"(a));
    float ra = a - __uint_as_float(hi << 16);
    float rb = b - __uint_as_float(hi & 0xFFFF0000u);
    asm("cvt.rn.bf16x2.f32 %0, %1, %2;" : "=r"(lo) : "f"(rb), "f"(ra));
}

__device__ __forceinline__ void ldmx4(u32* r, u32 addr) {
    asm volatile("ldmatrix.sync.aligned.m8n8.x4.shared.b16 {%0,%1,%2,%3}, [%4];"
                 : "=r"(r[0]), "=r"(r[1]), "=r"(r[2]), "=r"(r[3]) : "r"(addr));
}
__device__ __forceinline__ void mma16816(float* c, const u32* a, const u32* b) {
    asm volatile(
        "mma.sync.aligned.m16n8k16.row.col.f32.bf16.bf16.f32 "
        "{%0,%1,%2,%3}, {%4,%5,%6,%7}, {%8,%9}, {%0,%1,%2,%3};"
        : "+f"(c[0]), "+f"(c[1]), "+f"(c[2]), "+f"(c[3])
        : "r"(a[0]), "r"(a[1]), "r"(a[2]), "r"(a[3]), "r"(b[0]), "r"(b[1]));
}
__device__ __forceinline__ void cp16(u32 dst, const void* src) {
    asm volatile("cp.async.cg.shared.global [%0], [%1], 16;"
                 :: "r"(dst), "l"(__cvta_generic_to_global(src)));
}
// 256-byte bulk async copy, completion via mbarrier complete_tx
__device__ __forceinline__ void cpbulk256(u32 dst, const void* src, u32 mbar) {
    asm volatile(
        "cp.async.bulk.shared::cta.global.mbarrier::complete_tx::bytes "
        "[%0], [%1], 256, [%2];"
        :: "r"(dst), "l"(__cvta_generic_to_global(src)), "r"(mbar) : "memory");
}

// =====================================================================
// Weight prep (single launch): all 4 weights transposed + split.
// =====================================================================
__global__ void __launch_bounds__(256) prep_all(
    const float* __restrict__ Wb1, const float* __restrict__ Wb2,
    const float* __restrict__ Wt0, const float* __restrict__ Wt1,
    u16* __restrict__ b1h, u16* __restrict__ b1l,
    u16* __restrict__ b2h, u16* __restrict__ b2l,
    u16* __restrict__ t0h, u16* __restrict__ t0l,
    u16* __restrict__ t1h, u16* __restrict__ t1l)
{
    const int i = blockIdx.x * 256 + threadIdx.x;
    const float* W; u16 *H, *L; int N, Kreal, Kpad, li;
    if (i < 16384)      { W = Wb1; H = b1h; L = b1l; N = 256; Kreal = 512; Kpad = 512; li = i; }
    else if (i < 18432) { W = Wb2; H = b2h; L = b2l; N =  64; Kreal = 256; Kpad = 256; li = i - 16384; }
    else if (i < 45056) { W = Wt0; H = t0h; L = t0l; N = 512; Kreal = 415; Kpad = 416; li = i - 18432; }
    else if (i < 61440) { W = Wt1; H = t1h; L = t1l; N = 256; Kreal = 512; Kpad = 512; li = i - 45056; }
    else return;
    const int n  = li / (Kpad / 8);
    const int k8 = (li % (Kpad / 8)) * 8;
    u16 hb[8], lb[8];
#pragma unroll
    for (int j = 0; j < 8; j++) {
        const int k = k8 + j;
        const float w = (k < Kreal) ? W[(size_t)k * N + n] : 0.f;
        u32 h, l;
        split2(w, 0.f, h, l);
        hb[j] = (u16)(h & 0xFFFFu);
        lb[j] = (u16)(l & 0xFFFFu);
    }
    *(uint4*)(H + (size_t)n * Kpad + k8) = *(uint4*)hb;
    *(uint4*)(L + (size_t)n * Kpad + k8) = *(uint4*)lb;
}

// =====================================================================
// Warp-MMA split-bf16 GEMM (proven mainloop).
// OMODE: 0 = fp32 C; 1 = split bf16; 2 = both; 3 = fused final sigmoid.
// =====================================================================
template<int THREADS, int BN, int OMODE, int NSTAGE>
__global__ void __launch_bounds__(THREADS, (THREADS == 256 ? 2 : 1))
gemm_mma(
    const u16* __restrict__ Ah, const u16* __restrict__ Al, int Kpad,
    const u16* __restrict__ Bh, const u16* __restrict__ Bl,
    const float* __restrict__ bias,
    float* __restrict__ C, int ldc,
    u16* __restrict__ Oh, u16* __restrict__ Ol, int Kout,
    int NC,
    float* __restrict__ out2, const float* __restrict__ w2,
    const float* __restrict__ b2)
{
    constexpr int SR  = 40;
    constexpr int WNC = THREADS / 128;
    constexpr int NW  = BN / WNC;
    constexpr int NFR = NW / 8;
    constexpr int SSZ = (256 + 2 * BN) * SR;
    extern __shared__ u16 sm[];
    const u32 sbase = smem_u32(sm);
    const int tid = threadIdx.x, wid = tid >> 5, lane = tid & 31;
    const int wm = wid & 3, wn = wid >> 2;
    const int bm = blockIdx.y * 128, bn = blockIdx.x * BN;

    float acc[2][NFR][4];
#pragma unroll
    for (int m = 0; m < 2; m++)
#pragma unroll
        for (int n = 0; n < NFR; n++)
#pragma unroll
            for (int j = 0; j < 4; j++) acc[m][n][j] = 0.f;

    auto prefetch = [&](int c, int buf) {
        const u32 sb = sbase + (u32)buf * SSZ * 2;
        constexpr int AOPS = 1024 / THREADS;
#pragma unroll
        for (int i = 0; i < AOPS; i++) {
            const int g = tid + i * THREADS;
            const int arr = g >> 9, r = (g >> 2) & 127, ch = g & 3;
            const u16* src = (arr ? Al : Ah) + (size_t)(bm + r) * Kpad + c * 32 + ch * 8;
            cp16(sb + (u32)(arr * 128 * SR + r * SR + ch * 8) * 2, src);
        }
        constexpr int BOPS = BN * 8 / THREADS;
#pragma unroll
        for (int i = 0; i < BOPS; i++) {
            const int g = tid + i * THREADS;
            const int arr = g / (BN * 4), r = (g >> 2) & (BN - 1), ch = g & 3;
            const u16* src = (arr ? Bl : Bh) + (size_t)(bn + r) * Kpad + c * 32 + ch * 8;
            cp16(sb + (u32)((256 + arr * BN) * SR + r * SR + ch * 8) * 2, src);
        }
    };

    prefetch(0, 0);
    asm volatile("cp.async.commit_group;" ::: "memory");
    if (NSTAGE == 3) {
        prefetch(1, 1);
        asm volatile("cp.async.commit_group;" ::: "memory");
    }

    for (int c = 0; c < NC; c++) {
        asm volatile("cp.async.wait_group %0;" :: "n"(NSTAGE - 2) : "memory");
        __syncthreads();
        if (c + NSTAGE - 1 < NC) prefetch(c + NSTAGE - 1, (c + NSTAGE - 1) % NSTAGE);
        asm volatile("cp.async.commit_group;" ::: "memory");

        const u32 sA  = sbase + (u32)(c % NSTAGE) * SSZ * 2;
        const u32 sBs = sA + 256 * SR * 2;
#pragma unroll
        for (int ks = 0; ks < 2; ks++) {
            u32 ah[2][4], al_[2][4];
#pragma unroll
            for (int mf = 0; mf < 2; mf++) {
                const u32 ra = sA + (u32)(((wm * 32 + mf * 16 + (lane & 15)) * SR
                                           + ks * 16 + (lane >> 4) * 8) * 2);
                ldmx4(ah[mf], ra);
                ldmx4(al_[mf], ra + 128 * SR * 2);
            }
#pragma unroll
            for (int nf2 = 0; nf2 < NFR / 2; nf2++) {
                const u32 rb = sBs + (u32)(((wn * NW + nf2 * 16 + (lane & 7)
                                             + ((lane >> 4) << 3)) * SR
                                            + ks * 16 + ((lane >> 3) & 1) * 8) * 2);
                u32 bh4[4], bl4[4];
                ldmx4(bh4, rb);
                ldmx4(bl4, rb + BN * SR * 2);
#pragma unroll
                for (int hf = 0; hf < 2; hf++) {
                    const int nf = nf2 * 2 + hf;
                    const u32* bh2 = bh4 + hf * 2;
                    const u32* bl2 = bl4 + hf * 2;
#pragma unroll
                    for (int mf = 0; mf < 2; mf++) {
                        mma16816(acc[mf][nf], ah[mf],  bh2);
                        mma16816(acc[mf][nf], ah[mf],  bl2);
                        mma16816(acc[mf][nf], al_[mf], bh2);
                    }
                }
            }
        }
    }

    if (OMODE == 3) {
        asm volatile("cp.async.wait_group 0;" ::: "memory");
        __syncthreads();
        float* srow = (float*)sm;
        if (tid < 128) srow[tid] = 0.f;
        __syncthreads();
        float p[4] = {0.f, 0.f, 0.f, 0.f};
#pragma unroll
        for (int mf = 0; mf < 2; mf++) {
#pragma unroll
            for (int nf = 0; nf < NFR; nf++) {
                const int cc = bn + wn * NW + nf * 8 + 2 * (lane & 3);
                const float b0 = bias[cc], b1 = bias[cc + 1];
                const float w0 = w2[cc], w1 = w2[cc + 1];
                const float v0 = fmaxf(acc[mf][nf][0] + b0, 0.f);
                const float v1 = fmaxf(acc[mf][nf][1] + b1, 0.f);
                const float v2 = fmaxf(acc[mf][nf][2] + b0, 0.f);
                const float v3 = fmaxf(acc[mf][nf][3] + b1, 0.f);
                p[mf * 2 + 0] += v0 * w0 + v1 * w1;
                p[mf * 2 + 1] += v2 * w0 + v3 * w1;
            }
        }
#pragma unroll
        for (int s = 1; s <= 2; s <<= 1)
#pragma unroll
            for (int j = 0; j < 4; j++)
                p[j] += __shfl_xor_sync(0xffffffffu, p[j], s);
        if ((lane & 3) == 0) {
            const int r0 = wm * 32 + (lane >> 2);
            atomicAdd(&srow[r0],      p[0]);
            atomicAdd(&srow[r0 + 8],  p[1]);
            atomicAdd(&srow[r0 + 16], p[2]);
            atomicAdd(&srow[r0 + 24], p[3]);
        }
        __syncthreads();
        if (tid < 128)
            out2[bm + tid] = 1.f / (1.f + expf(-(srow[tid] + b2[0])));
    } else {
#pragma unroll
        for (int mf = 0; mf < 2; mf++) {
#pragma unroll
            for (int nf = 0; nf < NFR; nf++) {
                const int row0 = bm + wm * 32 + mf * 16 + (lane >> 2);
                const int cc   = bn + wn * NW + nf * 8 + 2 * (lane & 3);
                const float b0 = bias[cc], b1 = bias[cc + 1];
                const float v0 = fmaxf(acc[mf][nf][0] + b0, 0.f);
                const float v1 = fmaxf(acc[mf][nf][1] + b1, 0.f);
                const float v2 = fmaxf(acc[mf][nf][2] + b0, 0.f);
                const float v3 = fmaxf(acc[mf][nf][3] + b1, 0.f);
                if (OMODE != 1) {
                    *(float2*)(C + (size_t)row0 * ldc + cc)       = make_float2(v0, v1);
                    *(float2*)(C + (size_t)(row0 + 8) * ldc + cc) = make_float2(v2, v3);
                }
                if (OMODE != 0) {
                    u32 h, l;
                    split2(v0, v1, h, l);
                    *(u32*)(Oh + (size_t)row0 * Kout + cc) = h;
                    *(u32*)(Ol + (size_t)row0 * Kout + cc) = l;
                    split2(v2, v3, h, l);
                    *(u32*)(Oh + (size_t)(row0 + 8) * Kout + cc) = h;
                    *(u32*)(Ol + (size_t)(row0 + 8) * Kout + cc) = l;
                }
            }
        }
    }
}

// =====================================================================
// Bottom MLP layer 0: x0 = relu(dense[16384,13] @ Wb0 + bb0), split-bf16 out
// =====================================================================
__global__ void __launch_bounds__(256) bot0_kernel(
    const float* __restrict__ dense, const float* __restrict__ W,
    const float* __restrict__ bias, u16* __restrict__ xh, u16* __restrict__ xl)
{
    __shared__ float sW[13 * 512];
    __shared__ float sB[512];
    __shared__ float sD[32 * 13];
    const int tid = threadIdx.x;
    const int rbase = blockIdx.x * 32;

    for (int i = tid; i < 13 * 512; i += 256) sW[i] = W[i];
    for (int i = tid; i < 512;      i += 256) sB[i] = bias[i];
    for (int i = tid; i < 32 * 13;  i += 256) sD[i] = dense[(size_t)rbase * 13 + i];
    __syncthreads();

    const int q  = tid & 127;
    const int rs = tid >> 7;
    const int c0 = q * 4;

    float4 w[13];
#pragma unroll
    for (int k = 0; k < 13; k++) w[k] = *(const float4*)&sW[k * 512 + c0];
    const float4 bq = *(const float4*)&sB[c0];

    for (int rr = 0; rr < 16; rr++) {
        const int r = rs * 16 + rr;
        float4 acc = bq;
#pragma unroll
        for (int k = 0; k < 13; k++) {
            const float a = sD[r * 13 + k];
            acc.x += a * w[k].x; acc.y += a * w[k].y;
            acc.z += a * w[k].z; acc.w += a * w[k].w;
        }
        acc.x = fmaxf(acc.x, 0.f); acc.y = fmaxf(acc.y, 0.f);
        acc.z = fmaxf(acc.z, 0.f); acc.w = fmaxf(acc.w, 0.f);
        u32 h0, l0, h1, l1;
        split2(acc.x, acc.y, h0, l0);
        split2(acc.z, acc.w, h1, l1);
        const size_t o = (size_t)(rbase + r) * 512 + c0;
        *(uint2*)(xh + o) = make_uint2(h0, h1);
        *(uint2*)(xl + o) = make_uint2(l0, l1);
    }
}

// =====================================================================
// Embedding gather (cp.async.bulk, 256B per op) + pairwise interaction.
// 27 bulk copies per row (26 emb + d). 4x4 vector tiles, split-bf16 out
// into hh/hl (cols 64..414, stride 416).
// =====================================================================
#define EROWS 8

__global__ void __launch_bounds__(256) embed_interact3(
    const u64* __restrict__ sidx, const float* __restrict__ emb,
    const float* __restrict__ dvec,
    u16* __restrict__ hh, u16* __restrict__ hl)
{
    extern __shared__ float Tsh[];
    __shared__ u64 mbar_store;
    __shared__ int s_is32;
    float4* T4 = (float4*)Tsh;
    const u32 sbase = smem_u32(Tsh);
    const u32 mbar  = smem_u32(&mbar_store);
    const int tid = threadIdx.x;
    const int rbase = blockIdx.x * EROWS;

    if (tid == 0) {
        int f = 0;
#pragma unroll
        for (int i = 0; i < 16; i++)
            if (sidx[i] >> 32) f = 1;
        s_is32 = f;
        asm volatile("mbarrier.init.shared.b64 [%0], 1;" :: "r"(mbar) : "memory");
    }
    __syncthreads();
    if (tid == 0) {
        asm volatile("mbarrier.arrive.expect_tx.shared.b64 _, [%0], %1;"
                     :: "r"(mbar), "r"((u32)((EROWS * 27) * 256)) : "memory");
    }
    __syncthreads();
    const bool is32 = (s_is32 != 0);
    const int* sidx32 = (const int*)sidx;

    if (tid < EROWS * 26) {
        const int r = tid / 26, t = tid - r * 26;
        long long idx;
        if (is32) idx = (long long)sidx32[(rbase + r) * 26 + t];
        else      idx = (long long)sidx[(rbase + r) * 26 + t];
        cpbulk256(sbase + (u32)((r * 28 + t) * 272),
                  emb + ((size_t)t * VOCABSZ + (size_t)idx) * 64, mbar);
    } else if (tid < EROWS * 27) {
        const int r = tid - EROWS * 26;
        cpbulk256(sbase + (u32)((r * 28 + 26) * 272),
                  dvec + (size_t)(rbase + r) * 64, mbar);
    }
    // zero pad vector 27 (plain stores)
    for (int u = tid; u < EROWS * 16; u += 256) {
        const int r = u >> 4, f = u & 15;
        T4[(r * 28 + 27) * 17 + f] = make_float4(0.f, 0.f, 0.f, 0.f);
    }
    // wait for all bulk transactions (parity 0, acquire)
    {
        u32 done;
        asm volatile(
            "{\n\t.reg .pred p;\n\t"
            "mbarrier.try_wait.parity.acquire.cta.shared::cta.b64 p, [%1], 0;\n\t"
            "selp.b32 %0, 1, 0, p;\n\t}"
            : "=r"(done) : "r"(mbar) : "memory");
        if (!done) {
            asm volatile(
                "{\n\t.reg .pred P;\n"
                "WL_%=:\n\t"
                "mbarrier.try_wait.parity.acquire.cta.shared::cta.b64 P, [%0], 0, 0x989680;\n\t"
                "@P bra WD_%=;\n\t"
                "bra WL_%=;\n"
                "WD_%=:\n\t}"
                :: "r"(mbar) : "memory");
        }
    }
    __syncthreads();

    const int task = tid;
    if (task < EROWS * 28) {
        const int r = task / 28, tt = task - r * 28;
        const int grow = rbase + r;
        u16* hrh = hh + (size_t)grow * 416 + 64;
        u16* hrl = hl + (size_t)grow * 416 + 64;
        const float4* bb = T4 + (size_t)r * 28 * 17;

        if (tt < 21) {
            int ti = 1;
            while ((ti * (ti + 1)) / 2 <= tt) ti++;
            const int tj = tt - ti * (ti - 1) / 2;
            const float4* Ti = bb + (4 * ti) * 17;
            const float4* Tj = bb + (4 * tj) * 17;
            float a[4][4];
#pragma unroll
            for (int ii = 0; ii < 4; ii++)
#pragma unroll
                for (int jj = 0; jj < 4; jj++) a[ii][jj] = 0.f;
#pragma unroll
            for (int f = 0; f < 16; f++) {
                float4 x[4], y[4];
#pragma unroll
                for (int ii = 0; ii < 4; ii++) x[ii] = Ti[ii * 17 + f];
#pragma unroll
                for (int jj = 0; jj < 4; jj++) y[jj] = Tj[jj * 17 + f];
#pragma unroll
                for (int ii = 0; ii < 4; ii++)
#pragma unroll
                    for (int jj = 0; jj < 4; jj++)
                        a[ii][jj] += x[ii].x * y[jj].x + x[ii].y * y[jj].y
                                   + x[ii].z * y[jj].z + x[ii].w * y[jj].w;
            }
#pragma unroll
            for (int ii = 0; ii < 4; ii++) {
                const int i = 4 * ti + ii;
                if (i < 27) {
                    const int base_i = i * (i - 1) / 2;
#pragma unroll
                    for (int jj = 0; jj < 4; jj++) {
                        const int j = 4 * tj + jj;
                        u32 h, l;
                        split2(a[ii][jj], 0.f, h, l);
                        hrh[base_i + j] = (u16)h;
                        hrl[base_i + j] = (u16)l;
                    }
                }
            }
        } else {
            const int ti = tt - 21;
            const float4* Ti = bb + (4 * ti) * 17;
            float a[6];
#pragma unroll
            for (int p = 0; p < 6; p++) a[p] = 0.f;
#pragma unroll
            for (int f = 0; f < 16; f++) {
                float4 x[4];
#pragma unroll
                for (int ii = 0; ii < 4; ii++) x[ii] = Ti[ii * 17 + f];
                a[0] += x[1].x * x[0].x + x[1].y * x[0].y + x[1].z * x[0].z + x[1].w * x[0].w;
                a[1] += x[2].x * x[0].x + x[2].y * x[0].y + x[2].z * x[0].z + x[2].w * x[0].w;
                a[2] += x[2].x * x[1].x + x[2].y * x[1].y + x[2].z * x[1].z + x[2].w * x[1].w;
                a[3] += x[3].x * x[0].x + x[3].y * x[0].y + x[3].z * x[0].z + x[3].w * x[0].w;
                a[4] += x[3].x * x[1].x + x[3].y * x[1].y + x[3].z * x[1].z + x[3].w * x[1].w;
                a[5] += x[3].x * x[2].x + x[3].y * x[2].y + x[3].z * x[2].z + x[3].w * x[2].w;
            }
            const int pi[6] = {1, 2, 2, 3, 3, 3};
            const int pj[6] = {0, 0, 1, 0, 1, 2};
#pragma unroll
            for (int p = 0; p < 6; p++) {
                const int i = 4 * ti + pi[p], j = 4 * ti + pj[p];
                if (i < 27) {
                    u32 h, l;
                    split2(a[p], 0.f, h, l);
                    hrh[i * (i - 1) / 2 + j] = (u16)h;
                    hrl[i * (i - 1) / 2 + j] = (u16)l;
                }
            }
        }
    }
}

// =====================================================================
// launch (serial chain — R11 structure, Kpad=416)
// =====================================================================
extern "C" void kernel_launch(void* const* d_in, const int* in_sizes, int n_in,
                              void* d_out, int out_size)
{
    const float* dense = (const float*)d_in[0];
    const u64*   sidx  = (const u64*)  d_in[1];
    const float* emb   = (const float*)d_in[2];
    const float* Wb0 = (const float*)d_in[3];  const float* bb0 = (const float*)d_in[4];
    const float* Wb1 = (const float*)d_in[5];  const float* bb1 = (const float*)d_in[6];
    const float* Wb2 = (const float*)d_in[7];  const float* bb2 = (const float*)d_in[8];
    const float* Wt0 = (const float*)d_in[9];  const float* bt0 = (const float*)d_in[10];
    const float* Wt1 = (const float*)d_in[11]; const float* bt1 = (const float*)d_in[12];
    const float* Wt2 = (const float*)d_in[13]; const float* bt2 = (const float*)d_in[14];
    float* out = (float*)d_out;

    u16 *x0h, *x0l, *x1h, *x1l, *hh, *hl, *h1h, *h1l;
    float *dv;
    cudaGetSymbolAddress((void**)&x0h, g_x0h); cudaGetSymbolAddress((void**)&x0l, g_x0l);
    cudaGetSymbolAddress((void**)&x1h, g_x1h); cudaGetSymbolAddress((void**)&x1l, g_x1l);
    cudaGetSymbolAddress((void**)&dv,  g_d);
    cudaGetSymbolAddress((void**)&hh,  g_hh);  cudaGetSymbolAddress((void**)&hl,  g_hl);
    cudaGetSymbolAddress((void**)&h1h, g_h1h); cudaGetSymbolAddress((void**)&h1l, g_h1l);
    u16 *wb1h, *wb1l, *wb2h, *wb2l, *wt0h, *wt0l, *wt1h, *wt1l;
    cudaGetSymbolAddress((void**)&wb1h, g_Wb1h); cudaGetSymbolAddress((void**)&wb1l, g_Wb1l);
    cudaGetSymbolAddress((void**)&wb2h, g_Wb2h); cudaGetSymbolAddress((void**)&wb2l, g_Wb2l);
    cudaGetSymbolAddress((void**)&wt0h, g_Wt0h); cudaGetSymbolAddress((void**)&wt0l, g_Wt0l);
    cudaGetSymbolAddress((void**)&wt1h, g_Wt1h); cudaGetSymbolAddress((void**)&wt1l, g_Wt1l);

    // dynamic smem opt-in (idempotent, non-stream API: capture-safe)
    const int SM256 = 3 * (256 + 2 * 256) * 40 * 2;   // 184,320 B
    const int SM128 = 2 * (256 + 2 * 128) * 40 * 2;   //  81,920 B
    const int SM64  = 3 * (256 + 2 *  64) * 40 * 2;   //  92,160 B
    const int SMEI  = EROWS * 28 * 68 * 4;            //  60,928 B
    cudaFuncSetAttribute((const void*)gemm_mma<256, 128, 1, 2>,
                         cudaFuncAttributeMaxDynamicSharedMemorySize, SM128);
    cudaFuncSetAttribute((const void*)gemm_mma<512, 64, 2, 3>,
                         cudaFuncAttributeMaxDynamicSharedMemorySize, SM64);
    cudaFuncSetAttribute((const void*)gemm_mma<512, 256, 1, 3>,
                         cudaFuncAttributeMaxDynamicSharedMemorySize, SM256);
    cudaFuncSetAttribute((const void*)gemm_mma<512, 256, 3, 3>,
                         cudaFuncAttributeMaxDynamicSharedMemorySize, SM256);
    cudaFuncSetAttribute((const void*)embed_interact3,
                         cudaFuncAttributeMaxDynamicSharedMemorySize, SMEI);

    // 0) weight transpose + bf16 split
    prep_all<<<240, 256>>>(Wb1, Wb2, Wt0, Wt1,
                           wb1h, wb1l, wb2h, wb2l, wt0h, wt0l, wt1h, wt1l);

    // 1) bottom L0: dense -> x0 (split)
    bot0_kernel<<<BATCH / 32, 256>>>(dense, Wb0, bb0, x0h, x0l);

    // 2) bottom L1: x0 -> x1 (split out)  N=256 K=512
    gemm_mma<256, 128, 1, 2><<<dim3(2, BATCH / 128), 256, SM128>>>(
        x0h, x0l, 512, wb1h, wb1l, bb1, nullptr, 0, x1h, x1l, 256, 16,
        nullptr, nullptr, nullptr);

    // 3) bottom L2: x1 -> d fp32 + hh/hl cols 0..63  N=64 K=256
    gemm_mma<512, 64, 2, 3><<<dim3(1, BATCH / 128), 512, SM64>>>(
        x1h, x1l, 256, wb2h, wb2l, bb2, dv, 64, hh, hl, 416, 8,
        nullptr, nullptr, nullptr);

    // 4) embedding gather (bulk) + interaction -> hh/hl cols 64..414
    embed_interact3<<<BATCH / EROWS, 256, SMEI>>>(sidx, emb, dv, hh, hl);

    // 5) top L0: h -> h1 (split out)  N=512 K=416
    gemm_mma<512, 256, 1, 3><<<dim3(2, BATCH / 128), 512, SM256>>>(
        hh, hl, 416, wt0h, wt0l, bt0, nullptr, 0, h1h, h1l, 512, 13,
        nullptr, nullptr, nullptr);

    // 6) top L1 + final fused: h1 -> sigmoid(h2 . Wt2 + bt2) -> out
    gemm_mma<512, 256, 3, 3><<<dim3(1, BATCH / 128), 512, SM256>>>(
        h1h, h1l, 512, wt1h, wt1l, bt1, nullptr, 0, nullptr, nullptr, 0, 16,
        out, Wt2, bt2);
}

// round 14
// speedup vs baseline: 1.1580x; 1.0285x over previous
#include <cuda_runtime.h>
#include <cuda_bf16.h>
#include <math.h>

#define BATCH   16384
#define NTAB    26
#define VOCABSZ 100000

typedef unsigned long long u64;
typedef unsigned int       u32;
typedef unsigned short     u16;

// ---------------- scratch (bss, zero-initialized, no allocation) --------
__device__ u16   g_x0h[BATCH * 512], g_x0l[BATCH * 512];   // bottom L0 out (split)
__device__ u16   g_x1h[BATCH * 256], g_x1l[BATCH * 256];   // bottom L1 out (split)
__device__ float g_d  [BATCH * 64];                        // bottom L2 out (fp32 d)
__device__ u16   g_hh [BATCH * 448], g_hl [BATCH * 448];   // split h (d|inter|zero pad)
__device__ u16   g_h1h[BATCH * 512], g_h1l[BATCH * 512];   // top L0 out (split)
// transposed + split bf16 weights  (Wt[n][k] = W[k][n]; k >= Kreal zeroed)
__device__ u16 g_Wb1h[256 * 512], g_Wb1l[256 * 512];
__device__ u16 g_Wb2h[ 64 * 256], g_Wb2l[ 64 * 256];
__device__ u16 g_Wt0h[512 * 448], g_Wt0l[512 * 448];
__device__ u16 g_Wt1h[256 * 512], g_Wt1l[256 * 512];

// ---------------- helpers ----------------
__device__ __forceinline__ u32 smem_u32(const void* p) {
    u32 a;
    asm("{ .reg .u64 t; cvta.to.shared.u64 t, %1; cvt.u32.u64 %0, t; }"
        : "=r"(a) : "l"(p));
    return a;
}

// split fp32 pair (a,b) into packed bf16 hi (a->lo half) and bf16 residuals
__device__ __forceinline__ void split2(float a, float b, u32& hi, u32& lo) {
    asm("cvt.rn.bf16x2.f32 %0, %1, %2;" : "=r"(hi) : "f"(b), "f"(a));
    float ra = a - __uint_as_float(hi << 16);
    float rb = b - __uint_as_float(hi & 0xFFFF0000u);
    asm("cvt.rn.bf16x2.f32 %0, %1, %2;" : "=r"(lo) : "f"(rb), "f"(ra));
}

__device__ __forceinline__ void ldmx4(u32* r, u32 addr) {
    asm volatile("ldmatrix.sync.aligned.m8n8.x4.shared.b16 {%0,%1,%2,%3}, [%4];"
                 : "=r"(r[0]), "=r"(r[1]), "=r"(r[2]), "=r"(r[3]) : "r"(addr));
}
__device__ __forceinline__ void mma16816(float* c, const u32* a, const u32* b) {
    asm volatile(
        "mma.sync.aligned.m16n8k16.row.col.f32.bf16.bf16.f32 "
        "{%0,%1,%2,%3}, {%4,%5,%6,%7}, {%8,%9}, {%0,%1,%2,%3};"
        : "+f"(c[0]), "+f"(c[1]), "+f"(c[2]), "+f"(c[3])
        : "r"(a[0]), "r"(a[1]), "r"(a[2]), "r"(a[3]), "r"(b[0]), "r"(b[1]));
}
__device__ __forceinline__ void cp16(u32 dst, const void* src) {
    asm volatile("cp.async.cg.shared.global [%0], [%1], 16;"
                 :: "r"(dst), "l"(__cvta_generic_to_global(src)));
}
// 256-byte bulk async copy, completion via mbarrier complete_tx
__device__ __forceinline__ void cpbulk256(u32 dst, const void* src, u32 mbar) {
    asm volatile(
        "cp.async.bulk.shared::cta.global.mbarrier::complete_tx::bytes "
        "[%0], [%1], 256, [%2];"
        :: "r"(dst), "l"(__cvta_generic_to_global(src)), "r"(mbar) : "memory");
}

// =====================================================================
// Weight prep (single launch): all 4 weights transposed + split.
// =====================================================================
__global__ void __launch_bounds__(256) prep_all(
    const float* __restrict__ Wb1, const float* __restrict__ Wb2,
    const float* __restrict__ Wt0, const float* __restrict__ Wt1,
    u16* __restrict__ b1h, u16* __restrict__ b1l,
    u16* __restrict__ b2h, u16* __restrict__ b2l,
    u16* __restrict__ t0h, u16* __restrict__ t0l,
    u16* __restrict__ t1h, u16* __restrict__ t1l)
{
    const int i = blockIdx.x * 256 + threadIdx.x;
    const float* W; u16 *H, *L; int N, Kreal, Kpad, li;
    if (i < 16384)      { W = Wb1; H = b1h; L = b1l; N = 256; Kreal = 512; Kpad = 512; li = i; }
    else if (i < 18432) { W = Wb2; H = b2h; L = b2l; N =  64; Kreal = 256; Kpad = 256; li = i - 16384; }
    else if (i < 47104) { W = Wt0; H = t0h; L = t0l; N = 512; Kreal = 415; Kpad = 448; li = i - 18432; }
    else if (i < 63488) { W = Wt1; H = t1h; L = t1l; N = 256; Kreal = 512; Kpad = 512; li = i - 47104; }
    else return;
    const int n  = li / (Kpad / 8);
    const int k8 = (li % (Kpad / 8)) * 8;
    u16 hb[8], lb[8];
#pragma unroll
    for (int j = 0; j < 8; j++) {
        const int k = k8 + j;
        const float w = (k < Kreal) ? W[(size_t)k * N + n] : 0.f;
        u32 h, l;
        split2(w, 0.f, h, l);
        hb[j] = (u16)(h & 0xFFFFu);
        lb[j] = (u16)(l & 0xFFFFu);
    }
    *(uint4*)(H + (size_t)n * Kpad + k8) = *(uint4*)hb;
    *(uint4*)(L + (size_t)n * Kpad + k8) = *(uint4*)lb;
}

// =====================================================================
// Warp-MMA split-bf16 GEMM (proven mainloop).
// OMODE: 0 = fp32 C; 1 = split bf16; 2 = both; 3 = fused final sigmoid.
// =====================================================================
template<int THREADS, int BN, int OMODE, int NSTAGE>
__global__ void __launch_bounds__(THREADS, (THREADS == 256 ? 2 : 1))
gemm_mma(
    const u16* __restrict__ Ah, const u16* __restrict__ Al, int Kpad,
    const u16* __restrict__ Bh, const u16* __restrict__ Bl,
    const float* __restrict__ bias,
    float* __restrict__ C, int ldc,
    u16* __restrict__ Oh, u16* __restrict__ Ol, int Kout,
    int NC,
    float* __restrict__ out2, const float* __restrict__ w2,
    const float* __restrict__ b2)
{
    constexpr int SR  = 40;
    constexpr int WNC = THREADS / 128;
    constexpr int NW  = BN / WNC;
    constexpr int NFR = NW / 8;
    constexpr int SSZ = (256 + 2 * BN) * SR;
    extern __shared__ u16 sm[];
    const u32 sbase = smem_u32(sm);
    const int tid = threadIdx.x, wid = tid >> 5, lane = tid & 31;
    const int wm = wid & 3, wn = wid >> 2;
    const int bm = blockIdx.y * 128, bn = blockIdx.x * BN;

    float acc[2][NFR][4];
#pragma unroll
    for (int m = 0; m < 2; m++)
#pragma unroll
        for (int n = 0; n < NFR; n++)
#pragma unroll
            for (int j = 0; j < 4; j++) acc[m][n][j] = 0.f;

    auto prefetch = [&](int c, int buf) {
        const u32 sb = sbase + (u32)buf * SSZ * 2;
        constexpr int AOPS = 1024 / THREADS;
#pragma unroll
        for (int i = 0; i < AOPS; i++) {
            const int g = tid + i * THREADS;
            const int arr = g >> 9, r = (g >> 2) & 127, ch = g & 3;
            const u16* src = (arr ? Al : Ah) + (size_t)(bm + r) * Kpad + c * 32 + ch * 8;
            cp16(sb + (u32)(arr * 128 * SR + r * SR + ch * 8) * 2, src);
        }
        constexpr int BOPS = BN * 8 / THREADS;
#pragma unroll
        for (int i = 0; i < BOPS; i++) {
            const int g = tid + i * THREADS;
            const int arr = g / (BN * 4), r = (g >> 2) & (BN - 1), ch = g & 3;
            const u16* src = (arr ? Bl : Bh) + (size_t)(bn + r) * Kpad + c * 32 + ch * 8;
            cp16(sb + (u32)((256 + arr * BN) * SR + r * SR + ch * 8) * 2, src);
        }
    };

    prefetch(0, 0);
    asm volatile("cp.async.commit_group;" ::: "memory");
    if (NSTAGE == 3) {
        prefetch(1, 1);
        asm volatile("cp.async.commit_group;" ::: "memory");
    }

    for (int c = 0; c < NC; c++) {
        asm volatile("cp.async.wait_group %0;" :: "n"(NSTAGE - 2) : "memory");
        __syncthreads();
        if (c + NSTAGE - 1 < NC) prefetch(c + NSTAGE - 1, (c + NSTAGE - 1) % NSTAGE);
        asm volatile("cp.async.commit_group;" ::: "memory");

        const u32 sA  = sbase + (u32)(c % NSTAGE) * SSZ * 2;
        const u32 sBs = sA + 256 * SR * 2;
#pragma unroll
        for (int ks = 0; ks < 2; ks++) {
            u32 ah[2][4], al_[2][4];
#pragma unroll
            for (int mf = 0; mf < 2; mf++) {
                const u32 ra = sA + (u32)(((wm * 32 + mf * 16 + (lane & 15)) * SR
                                           + ks * 16 + (lane >> 4) * 8) * 2);
                ldmx4(ah[mf], ra);
                ldmx4(al_[mf], ra + 128 * SR * 2);
            }
#pragma unroll
            for (int nf2 = 0; nf2 < NFR / 2; nf2++) {
                const u32 rb = sBs + (u32)(((wn * NW + nf2 * 16 + (lane & 7)
                                             + ((lane >> 4) << 3)) * SR
                                            + ks * 16 + ((lane >> 3) & 1) * 8) * 2);
                u32 bh4[4], bl4[4];
                ldmx4(bh4, rb);
                ldmx4(bl4, rb + BN * SR * 2);
#pragma unroll
                for (int hf = 0; hf < 2; hf++) {
                    const int nf = nf2 * 2 + hf;
                    const u32* bh2 = bh4 + hf * 2;
                    const u32* bl2 = bl4 + hf * 2;
#pragma unroll
                    for (int mf = 0; mf < 2; mf++) {
                        mma16816(acc[mf][nf], ah[mf],  bh2);
                        mma16816(acc[mf][nf], ah[mf],  bl2);
                        mma16816(acc[mf][nf], al_[mf], bh2);
                    }
                }
            }
        }
    }

    if (OMODE == 3) {
        asm volatile("cp.async.wait_group 0;" ::: "memory");
        __syncthreads();
        float* srow = (float*)sm;
        if (tid < 128) srow[tid] = 0.f;
        __syncthreads();
        float p[4] = {0.f, 0.f, 0.f, 0.f};
#pragma unroll
        for (int mf = 0; mf < 2; mf++) {
#pragma unroll
            for (int nf = 0; nf < NFR; nf++) {
                const int cc = bn + wn * NW + nf * 8 + 2 * (lane & 3);
                const float b0 = bias[cc], b1 = bias[cc + 1];
                const float w0 = w2[cc], w1 = w2[cc + 1];
                const float v0 = fmaxf(acc[mf][nf][0] + b0, 0.f);
                const float v1 = fmaxf(acc[mf][nf][1] + b1, 0.f);
                const float v2 = fmaxf(acc[mf][nf][2] + b0, 0.f);
                const float v3 = fmaxf(acc[mf][nf][3] + b1, 0.f);
                p[mf * 2 + 0] += v0 * w0 + v1 * w1;
                p[mf * 2 + 1] += v2 * w0 + v3 * w1;
            }
        }
#pragma unroll
        for (int s = 1; s <= 2; s <<= 1)
#pragma unroll
            for (int j = 0; j < 4; j++)
                p[j] += __shfl_xor_sync(0xffffffffu, p[j], s);
        if ((lane & 3) == 0) {
            const int r0 = wm * 32 + (lane >> 2);
            atomicAdd(&srow[r0],      p[0]);
            atomicAdd(&srow[r0 + 8],  p[1]);
            atomicAdd(&srow[r0 + 16], p[2]);
            atomicAdd(&srow[r0 + 24], p[3]);
        }
        __syncthreads();
        if (tid < 128)
            out2[bm + tid] = 1.f / (1.f + expf(-(srow[tid] + b2[0])));
    } else {
#pragma unroll
        for (int mf = 0; mf < 2; mf++) {
#pragma unroll
            for (int nf = 0; nf < NFR; nf++) {
                const int row0 = bm + wm * 32 + mf * 16 + (lane >> 2);
                const int cc   = bn + wn * NW + nf * 8 + 2 * (lane & 3);
                const float b0 = bias[cc], b1 = bias[cc + 1];
                const float v0 = fmaxf(acc[mf][nf][0] + b0, 0.f);
                const float v1 = fmaxf(acc[mf][nf][1] + b1, 0.f);
                const float v2 = fmaxf(acc[mf][nf][2] + b0, 0.f);
                const float v3 = fmaxf(acc[mf][nf][3] + b1, 0.f);
                if (OMODE != 1) {
                    *(float2*)(C + (size_t)row0 * ldc + cc)       = make_float2(v0, v1);
                    *(float2*)(C + (size_t)(row0 + 8) * ldc + cc) = make_float2(v2, v3);
                }
                if (OMODE != 0) {
                    u32 h, l;
                    split2(v0, v1, h, l);
                    *(u32*)(Oh + (size_t)row0 * Kout + cc) = h;
                    *(u32*)(Ol + (size_t)row0 * Kout + cc) = l;
                    split2(v2, v3, h, l);
                    *(u32*)(Oh + (size_t)(row0 + 8) * Kout + cc) = h;
                    *(u32*)(Ol + (size_t)(row0 + 8) * Kout + cc) = l;
                }
            }
        }
    }
}

// =====================================================================
// Bottom MLP layer 0: x0 = relu(dense[16384,13] @ Wb0 + bb0), split-bf16 out
// =====================================================================
__global__ void __launch_bounds__(256) bot0_kernel(
    const float* __restrict__ dense, const float* __restrict__ W,
    const float* __restrict__ bias, u16* __restrict__ xh, u16* __restrict__ xl)
{
    __shared__ float sW[13 * 512];
    __shared__ float sB[512];
    __shared__ float sD[32 * 13];
    const int tid = threadIdx.x;
    const int rbase = blockIdx.x * 32;

    for (int i = tid; i < 13 * 512; i += 256) sW[i] = W[i];
    for (int i = tid; i < 512;      i += 256) sB[i] = bias[i];
    for (int i = tid; i < 32 * 13;  i += 256) sD[i] = dense[(size_t)rbase * 13 + i];
    __syncthreads();

    const int q  = tid & 127;
    const int rs = tid >> 7;
    const int c0 = q * 4;

    float4 w[13];
#pragma unroll
    for (int k = 0; k < 13; k++) w[k] = *(const float4*)&sW[k * 512 + c0];
    const float4 bq = *(const float4*)&sB[c0];

    for (int rr = 0; rr < 16; rr++) {
        const int r = rs * 16 + rr;
        float4 acc = bq;
#pragma unroll
        for (int k = 0; k < 13; k++) {
            const float a = sD[r * 13 + k];
            acc.x += a * w[k].x; acc.y += a * w[k].y;
            acc.z += a * w[k].z; acc.w += a * w[k].w;
        }
        acc.x = fmaxf(acc.x, 0.f); acc.y = fmaxf(acc.y, 0.f);
        acc.z = fmaxf(acc.z, 0.f); acc.w = fmaxf(acc.w, 0.f);
        u32 h0, l0, h1, l1;
        split2(acc.x, acc.y, h0, l0);
        split2(acc.z, acc.w, h1, l1);
        const size_t o = (size_t)(rbase + r) * 512 + c0;
        *(uint2*)(xh + o) = make_uint2(h0, h1);
        *(uint2*)(xl + o) = make_uint2(l0, l1);
    }
}

// =====================================================================
// Embedding gather (cp.async.bulk, 256B per op) + pairwise interaction.
// 27 bulk copies per row (26 emb + d). 4x4 vector tiles, split-bf16 out
// into hh/hl (cols 64..414, stride 448).
// =====================================================================
#define EROWS 8

__global__ void __launch_bounds__(256) embed_interact3(
    const u64* __restrict__ sidx, const float* __restrict__ emb,
    const float* __restrict__ dvec,
    u16* __restrict__ hh, u16* __restrict__ hl)
{
    extern __shared__ float Tsh[];
    __shared__ u64 mbar_store;
    __shared__ int s_is32;
    float4* T4 = (float4*)Tsh;
    const u32 sbase = smem_u32(Tsh);
    const u32 mbar  = smem_u32(&mbar_store);
    const int tid = threadIdx.x;
    const int rbase = blockIdx.x * EROWS;

    if (tid == 0) {
        int f = 0;
#pragma unroll
        for (int i = 0; i < 16; i++)
            if (sidx[i] >> 32) f = 1;
        s_is32 = f;
        asm volatile("mbarrier.init.shared.b64 [%0], 1;" :: "r"(mbar) : "memory");
    }
    __syncthreads();
    if (tid == 0) {
        asm volatile("mbarrier.arrive.expect_tx.shared.b64 _, [%0], %1;"
                     :: "r"(mbar), "r"((u32)((EROWS * 27) * 256)) : "memory");
    }
    __syncthreads();
    const bool is32 = (s_is32 != 0);
    const int* sidx32 = (const int*)sidx;

    if (tid < EROWS * 26) {
        const int r = tid / 26, t = tid - r * 26;
        long long idx;
        if (is32) idx = (long long)sidx32[(rbase + r) * 26 + t];
        else      idx = (long long)sidx[(rbase + r) * 26 + t];
        cpbulk256(sbase + (u32)((r * 28 + t) * 272),
                  emb + ((size_t)t * VOCABSZ + (size_t)idx) * 64, mbar);
    } else if (tid < EROWS * 27) {
        const int r = tid - EROWS * 26;
        cpbulk256(sbase + (u32)((r * 28 + 26) * 272),
                  dvec + (size_t)(rbase + r) * 64, mbar);
    }
    // zero pad vector 27 (plain stores)
    for (int u = tid; u < EROWS * 16; u += 256) {
        const int r = u >> 4, f = u & 15;
        T4[(r * 28 + 27) * 17 + f] = make_float4(0.f, 0.f, 0.f, 0.f);
    }
    // wait for all bulk transactions (parity 0, acquire)
    {
        u32 done;
        asm volatile(
            "{\n\t.reg .pred p;\n\t"
            "mbarrier.try_wait.parity.acquire.cta.shared::cta.b64 p, [%1], 0;\n\t"
            "selp.b32 %0, 1, 0, p;\n\t}"
            : "=r"(done) : "r"(mbar) : "memory");
        if (!done) {
            asm volatile(
                "{\n\t.reg .pred P;\n"
                "WL_%=:\n\t"
                "mbarrier.try_wait.parity.acquire.cta.shared::cta.b64 P, [%0], 0, 0x989680;\n\t"
                "@P bra WD_%=;\n\t"
                "bra WL_%=;\n"
                "WD_%=:\n\t}"
                :: "r"(mbar) : "memory");
        }
    }
    __syncthreads();

    const int task = tid;
    if (task < EROWS * 28) {
        const int r = task / 28, tt = task - r * 28;
        const int grow = rbase + r;
        u16* hrh = hh + (size_t)grow * 448 + 64;
        u16* hrl = hl + (size_t)grow * 448 + 64;
        const float4* bb = T4 + (size_t)r * 28 * 17;

        if (tt < 21) {
            int ti = 1;
            while ((ti * (ti + 1)) / 2 <= tt) ti++;
            const int tj = tt - ti * (ti - 1) / 2;
            const float4* Ti = bb + (4 * ti) * 17;
            const float4* Tj = bb + (4 * tj) * 17;
            float a[4][4];
#pragma unroll
            for (int ii = 0; ii < 4; ii++)
#pragma unroll
                for (int jj = 0; jj < 4; jj++) a[ii][jj] = 0.f;
#pragma unroll
            for (int f = 0; f < 16; f++) {
                float4 x[4], y[4];
#pragma unroll
                for (int ii = 0; ii < 4; ii++) x[ii] = Ti[ii * 17 + f];
#pragma unroll
                for (int jj = 0; jj < 4; jj++) y[jj] = Tj[jj * 17 + f];
#pragma unroll
                for (int ii = 0; ii < 4; ii++)
#pragma unroll
                    for (int jj = 0; jj < 4; jj++)
                        a[ii][jj] += x[ii].x * y[jj].x + x[ii].y * y[jj].y
                                   + x[ii].z * y[jj].z + x[ii].w * y[jj].w;
            }
#pragma unroll
            for (int ii = 0; ii < 4; ii++) {
                const int i = 4 * ti + ii;
                if (i < 27) {
                    const int base_i = i * (i - 1) / 2;
#pragma unroll
                    for (int jj = 0; jj < 4; jj++) {
                        const int j = 4 * tj + jj;
                        u32 h, l;
                        split2(a[ii][jj], 0.f, h, l);
                        hrh[base_i + j] = (u16)h;
                        hrl[base_i + j] = (u16)l;
                    }
                }
            }
        } else {
            const int ti = tt - 21;
            const float4* Ti = bb + (4 * ti) * 17;
            float a[6];
#pragma unroll
            for (int p = 0; p < 6; p++) a[p] = 0.f;
#pragma unroll
            for (int f = 0; f < 16; f++) {
                float4 x[4];
#pragma unroll
                for (int ii = 0; ii < 4; ii++) x[ii] = Ti[ii * 17 + f];
                a[0] += x[1].x * x[0].x + x[1].y * x[0].y + x[1].z * x[0].z + x[1].w * x[0].w;
                a[1] += x[2].x * x[0].x + x[2].y * x[0].y + x[2].z * x[0].z + x[2].w * x[0].w;
                a[2] += x[2].x * x[1].x + x[2].y * x[1].y + x[2].z * x[1].z + x[2].w * x[1].w;
                a[3] += x[3].x * x[0].x + x[3].y * x[0].y + x[3].z * x[0].z + x[3].w * x[0].w;
                a[4] += x[3].x * x[1].x + x[3].y * x[1].y + x[3].z * x[1].z + x[3].w * x[1].w;
                a[5] += x[3].x * x[2].x + x[3].y * x[2].y + x[3].z * x[2].z + x[3].w * x[2].w;
            }
            const int pi[6] = {1, 2, 2, 3, 3, 3};
            const int pj[6] = {0, 0, 1, 0, 1, 2};
#pragma unroll
            for (int p = 0; p < 6; p++) {
                const int i = 4 * ti + pi[p], j = 4 * ti + pj[p];
                if (i < 27) {
                    u32 h, l;
                    split2(a[p], 0.f, h, l);
                    hrh[i * (i - 1) / 2 + j] = (u16)h;
                    hrl[i * (i - 1) / 2 + j] = (u16)l;
                }
            }
        }
    }
}

// =====================================================================
// launch (serial chain, Kpad=448; top-L0 now BN=128 / 2 CTAs per SM)
// =====================================================================
extern "C" void kernel_launch(void* const* d_in, const int* in_sizes, int n_in,
                              void* d_out, int out_size)
{
    const float* dense = (const float*)d_in[0];
    const u64*   sidx  = (const u64*)  d_in[1];
    const float* emb   = (const float*)d_in[2];
    const float* Wb0 = (const float*)d_in[3];  const float* bb0 = (const float*)d_in[4];
    const float* Wb1 = (const float*)d_in[5];  const float* bb1 = (const float*)d_in[6];
    const float* Wb2 = (const float*)d_in[7];  const float* bb2 = (const float*)d_in[8];
    const float* Wt0 = (const float*)d_in[9];  const float* bt0 = (const float*)d_in[10];
    const float* Wt1 = (const float*)d_in[11]; const float* bt1 = (const float*)d_in[12];
    const float* Wt2 = (const float*)d_in[13]; const float* bt2 = (const float*)d_in[14];
    float* out = (float*)d_out;

    u16 *x0h, *x0l, *x1h, *x1l, *hh, *hl, *h1h, *h1l;
    float *dv;
    cudaGetSymbolAddress((void**)&x0h, g_x0h); cudaGetSymbolAddress((void**)&x0l, g_x0l);
    cudaGetSymbolAddress((void**)&x1h, g_x1h); cudaGetSymbolAddress((void**)&x1l, g_x1l);
    cudaGetSymbolAddress((void**)&dv,  g_d);
    cudaGetSymbolAddress((void**)&hh,  g_hh);  cudaGetSymbolAddress((void**)&hl,  g_hl);
    cudaGetSymbolAddress((void**)&h1h, g_h1h); cudaGetSymbolAddress((void**)&h1l, g_h1l);
    u16 *wb1h, *wb1l, *wb2h, *wb2l, *wt0h, *wt0l, *wt1h, *wt1l;
    cudaGetSymbolAddress((void**)&wb1h, g_Wb1h); cudaGetSymbolAddress((void**)&wb1l, g_Wb1l);
    cudaGetSymbolAddress((void**)&wb2h, g_Wb2h); cudaGetSymbolAddress((void**)&wb2l, g_Wb2l);
    cudaGetSymbolAddress((void**)&wt0h, g_Wt0h); cudaGetSymbolAddress((void**)&wt0l, g_Wt0l);
    cudaGetSymbolAddress((void**)&wt1h, g_Wt1h); cudaGetSymbolAddress((void**)&wt1l, g_Wt1l);

    // dynamic smem opt-in (idempotent, non-stream API: capture-safe)
    const int SM256 = 3 * (256 + 2 * 256) * 40 * 2;   // 184,320 B
    const int SM128 = 2 * (256 + 2 * 128) * 40 * 2;   //  81,920 B
    const int SM64  = 3 * (256 + 2 *  64) * 40 * 2;   //  92,160 B
    const int SMEI  = EROWS * 28 * 68 * 4;            //  60,928 B
    cudaFuncSetAttribute((const void*)gemm_mma<256, 128, 1, 2>,
                         cudaFuncAttributeMaxDynamicSharedMemorySize, SM128);
    cudaFuncSetAttribute((const void*)gemm_mma<512, 64, 2, 3>,
                         cudaFuncAttributeMaxDynamicSharedMemorySize, SM64);
    cudaFuncSetAttribute((const void*)gemm_mma<512, 256, 3, 3>,
                         cudaFuncAttributeMaxDynamicSharedMemorySize, SM256);
    cudaFuncSetAttribute((const void*)embed_interact3,
                         cudaFuncAttributeMaxDynamicSharedMemorySize, SMEI);

    // 0) weight transpose + bf16 split
    prep_all<<<248, 256>>>(Wb1, Wb2, Wt0, Wt1,
                           wb1h, wb1l, wb2h, wb2l, wt0h, wt0l, wt1h, wt1l);

    // 1) bottom L0: dense -> x0 (split)
    bot0_kernel<<<BATCH / 32, 256>>>(dense, Wb0, bb0, x0h, x0l);

    // 2) bottom L1: x0 -> x1 (split out)  N=256 K=512  [BN=128, 2 CTA/SM]
    gemm_mma<256, 128, 1, 2><<<dim3(2, BATCH / 128), 256, SM128>>>(
        x0h, x0l, 512, wb1h, wb1l, bb1, nullptr, 0, x1h, x1l, 256, 16,
        nullptr, nullptr, nullptr);

    // 3) bottom L2: x1 -> d fp32 + hh/hl cols 0..63  N=64 K=256
    gemm_mma<512, 64, 2, 3><<<dim3(1, BATCH / 128), 512, SM64>>>(
        x1h, x1l, 256, wb2h, wb2l, bb2, dv, 64, hh, hl, 448, 8,
        nullptr, nullptr, nullptr);

    // 4) embedding gather (bulk) + interaction -> hh/hl cols 64..414
    embed_interact3<<<BATCH / EROWS, 256, SMEI>>>(sidx, emb, dv, hh, hl);

    // 5) top L0: h -> h1 (split out)  N=512 K=448  [BN=128, 2 CTA/SM]
    gemm_mma<256, 128, 1, 2><<<dim3(4, BATCH / 128), 256, SM128>>>(
        hh, hl, 448, wt0h, wt0l, bt0, nullptr, 0, h1h, h1l, 512, 14,
        nullptr, nullptr, nullptr);

    // 6) top L1 + final fused: h1 -> sigmoid(h2 . Wt2 + bt2) -> out
    gemm_mma<512, 256, 3, 3><<<dim3(1, BATCH / 128), 512, SM256>>>(
        h1h, h1l, 512, wt1h, wt1l, bt1, nullptr, 0, nullptr, nullptr, 0, 16,
        out, Wt2, bt2);
}